// round 16
// baseline (speedup 1.0000x reference)
#include <cuda_runtime.h>

// MxAssemble: out[b,c,y,x] = sum_{dy,dx in [0,13)} aff[b, dy*13+dx, y, x] * in2zp[b, c, y+dy-6, x+dx-6]
// B=4, D=169, C=64, H=W=192, fp32.
// R15 structure (64x x 8y x 16ch tile, CPT=8, chunked dx A/B/C, apA
// double-buffered across dy) + MANUAL SOFTWARE PIPELINING of the smem quad
// loads across the channel loop: quads for c+1 issue before computing c,
// so LDS latency is covered by ~40 slots of independent work.

#define BB   4
#define CC   64
#define HH   192
#define WW   192
#define WIN  13
#define DD   169
#define HWSZ (HH*WW)

#define TW    64     // x pixels per block
#define TH    8      // y rows per block
#define CBLK  16     // channels per block
#define CPT   8      // channels per thread
#define XR    4      // x pixels per thread
#define SROWS (TH+12)   // 20
#define SPITCH 80       // floats per smem row (320B, 16B aligned)
#define CSTRIDE (SROWS * SPITCH)

typedef unsigned long long u64t;

__device__ __forceinline__ u64t ffma2(u64t a, u64t b, u64t c) {
    u64t d;
    asm("fma.rn.f32x2 %0, %1, %2, %3;" : "=l"(d) : "l"(a), "l"(b), "l"(c));
    return d;
}
__device__ __forceinline__ u64t packf2(float lo, float hi) {
    u64t d;
    asm("mov.b64 %0, {%1, %2};" : "=l"(d) : "f"(lo), "f"(hi));
    return d;
}
__device__ __forceinline__ void unpackf2(u64t v, float& lo, float& hi) {
    asm("mov.b64 {%0, %1}, %2;" : "=f"(lo), "=f"(hi) : "l"(v));
}

union QU { ulonglong2 u; float4 f; };

__global__ __launch_bounds__(256, 2)
void mxassemble_kernel(const float* __restrict__ aff,
                       const float* __restrict__ in2,
                       float* __restrict__ out)
{
    __shared__ __align__(16) float s[CBLK][SROWS][SPITCH];   // 102,400 B

    const int tx = threadIdx.x;      // 0..15  -> x group
    const int ty = threadIdx.y;      // 0..15
    const int yy = ty & 7;           // row within tile
    const int ch = ty >> 3;          // channel half (0/1)

    const int bx = blockIdx.x;       // 12 = 4 cgroups * 3 xtiles, cgroup fastest
    const int cg = bx & 3;
    const int xt = bx >> 2;
    const int yt = blockIdx.y;       // 0..23
    const int b  = blockIdx.z;       // 0..3

    const int x0 = xt * TW;
    const int y0 = yt * TH;
    const int c0 = cg * CBLK;

    // ---- preload dy=0 chunk-A aff operands (independent of smem fill) -----
    const int xs = tx * XR;
    const float* affRow = aff + (size_t)b * DD * HWSZ + (y0 + yy) * WW + x0 + xs;

    ulonglong2 apA[4];
    #pragma unroll
    for (int j = 0; j < 4; j++)
        apA[j] = *(const ulonglong2*)(affRow + j * HWSZ);

    // ---- cooperative smem fill -------------------------------------------
    // 6400 quads = 16 planes x 20 rows x 20 aligned global quads (gxq = x0-8+4q).
    {
        const float* in2b = in2 + (size_t)b * CC * HWSZ;
        const int tid = ty * 16 + tx;
        int q  = tid % 20;
        int t2 = tid / 20;
        int rr = t2 % 20;
        int cc = t2 / 20;
        #pragma unroll 1
        for (int it = 0; it < 25; it++) {
            const int gy  = y0 - 6 + rr;
            const int gxq = x0 - 8 + 4 * q;

            float4 v = make_float4(0.f, 0.f, 0.f, 0.f);
            if ((unsigned)gy < (unsigned)HH) {
                const float* src = in2b + (size_t)(c0 + cc) * HWSZ + gy * WW + gxq;
                if (gxq >= 0 && gxq <= WW - 4) {
                    v = *(const float4*)src;
                } else {
                    if ((unsigned)(gxq + 0) < (unsigned)WW) v.x = src[0];
                    if ((unsigned)(gxq + 1) < (unsigned)WW) v.y = src[1];
                    if ((unsigned)(gxq + 2) < (unsigned)WW) v.z = src[2];
                    if ((unsigned)(gxq + 3) < (unsigned)WW) v.w = src[3];
                }
            }
            const int c0q = 4 * q - 2;               // smem col of v.x
            float* dst = &s[cc][rr][0];
            if (c0q >= 0) *(float2*)(dst + c0q) = make_float2(v.x, v.y);
            *(float2*)(dst + c0q + 2) = make_float2(v.z, v.w);

            // advance by 256 quads: 256 = 12*20 + 16
            q += 16; rr += 12;
            if (q >= 20)  { q -= 20; rr += 1; }
            if (rr >= 20) { rr -= 20; cc += 1; }
        }
    }
    __syncthreads();

    // ---- main accumulation ------------------------------------------------
    u64t accA[CPT], accB[CPT];       // accA: outputs (xs, xs+1), accB: (xs+2, xs+3)
    #pragma unroll
    for (int c = 0; c < CPT; c++) { accA[c] = 0ull; accB[c] = 0ull; }

    const float* sdy = &s[ch * CPT][0][0] + yy * SPITCH + xs;   // rolling smem base

    #pragma unroll 1
    for (int dy = 0; dy < WIN; dy++) {
        // issue chunk-B aff loads (consumed after chunk A, ~150 slots later)
        ulonglong2 apB[4];
        #pragma unroll
        for (int j = 0; j < 4; j++)
            apB[j] = *(const ulonglong2*)(affRow + (4 + j) * HWSZ);

        // ======== chunk A: j = 0..3 (quads Q0,Q1), c-pipelined =============
        {
            QU c0q, c1q, n0q, n1q;
            c0q.u = *(const ulonglong2*)(sdy);
            c1q.u = *(const ulonglong2*)(sdy + 4);
            #pragma unroll
            for (int c = 0; c < CPT; c++) {
                if (c < CPT - 1) {
                    n0q.u = *(const ulonglong2*)(sdy + (c + 1) * CSTRIDE);
                    n1q.u = *(const ulonglong2*)(sdy + (c + 1) * CSTRIDE + 4);
                }
                const u64t p0 = c0q.u.x, p2 = c0q.u.y, p4 = c1q.u.x;
                const u64t p1 = packf2(c0q.f.y, c0q.f.z);
                const u64t p3 = packf2(c0q.f.w, c1q.f.x);
                const u64t p5 = packf2(c1q.f.y, c1q.f.z);
                accA[c] = ffma2(apA[0].x, p0, accA[c]);  accB[c] = ffma2(apA[0].y, p2, accB[c]);
                accA[c] = ffma2(apA[1].x, p1, accA[c]);  accB[c] = ffma2(apA[1].y, p3, accB[c]);
                accA[c] = ffma2(apA[2].x, p2, accA[c]);  accB[c] = ffma2(apA[2].y, p4, accB[c]);
                accA[c] = ffma2(apA[3].x, p3, accA[c]);  accB[c] = ffma2(apA[3].y, p5, accB[c]);
                c0q = n0q; c1q = n1q;   // pure renaming after unroll
            }
        }

        // issue chunk-C aff loads (consumed after chunk B)
        ulonglong2 apC[5];
        #pragma unroll
        for (int j = 0; j < 5; j++)
            apC[j] = *(const ulonglong2*)(affRow + (8 + j) * HWSZ);

        // prefetch next dy's chunk-A aff operands (consumed next iteration)
        if (dy < WIN - 1) {
            const float* nextRow = affRow + WIN * HWSZ;
            #pragma unroll
            for (int j = 0; j < 4; j++)
                apA[j] = *(const ulonglong2*)(nextRow + j * HWSZ);
        }

        // ======== chunk B: j = 4..7 (quads Q1,Q2), c-pipelined =============
        {
            QU c1q, c2q, n1q, n2q;
            c1q.u = *(const ulonglong2*)(sdy + 4);
            c2q.u = *(const ulonglong2*)(sdy + 8);
            #pragma unroll
            for (int c = 0; c < CPT; c++) {
                if (c < CPT - 1) {
                    n1q.u = *(const ulonglong2*)(sdy + (c + 1) * CSTRIDE + 4);
                    n2q.u = *(const ulonglong2*)(sdy + (c + 1) * CSTRIDE + 8);
                }
                const u64t p4 = c1q.u.x, p6 = c1q.u.y, p8 = c2q.u.x;
                const u64t p5 = packf2(c1q.f.y, c1q.f.z);
                const u64t p7 = packf2(c1q.f.w, c2q.f.x);
                const u64t p9 = packf2(c2q.f.y, c2q.f.z);
                accA[c] = ffma2(apB[0].x, p4, accA[c]);  accB[c] = ffma2(apB[0].y, p6, accB[c]);
                accA[c] = ffma2(apB[1].x, p5, accA[c]);  accB[c] = ffma2(apB[1].y, p7, accB[c]);
                accA[c] = ffma2(apB[2].x, p6, accA[c]);  accB[c] = ffma2(apB[2].y, p8, accB[c]);
                accA[c] = ffma2(apB[3].x, p7, accA[c]);  accB[c] = ffma2(apB[3].y, p9, accB[c]);
                c1q = n1q; c2q = n2q;
            }
        }

        // ======== chunk C: j = 8..12 (quads Q2,Q3), c-pipelined ============
        {
            QU c2q, c3q, n2q, n3q;
            c2q.u = *(const ulonglong2*)(sdy + 8);
            c3q.u = *(const ulonglong2*)(sdy + 12);
            #pragma unroll
            for (int c = 0; c < CPT; c++) {
                if (c < CPT - 1) {
                    n2q.u = *(const ulonglong2*)(sdy + (c + 1) * CSTRIDE + 8);
                    n3q.u = *(const ulonglong2*)(sdy + (c + 1) * CSTRIDE + 12);
                }
                const u64t p8 = c2q.u.x, p10 = c2q.u.y, p12 = c3q.u.x, p14 = c3q.u.y;
                const u64t p9  = packf2(c2q.f.y, c2q.f.z);
                const u64t p11 = packf2(c2q.f.w, c3q.f.x);
                const u64t p13 = packf2(c3q.f.y, c3q.f.z);
                accA[c] = ffma2(apC[0].x, p8,  accA[c]);  accB[c] = ffma2(apC[0].y, p10, accB[c]);
                accA[c] = ffma2(apC[1].x, p9,  accA[c]);  accB[c] = ffma2(apC[1].y, p11, accB[c]);
                accA[c] = ffma2(apC[2].x, p10, accA[c]);  accB[c] = ffma2(apC[2].y, p12, accB[c]);
                accA[c] = ffma2(apC[3].x, p11, accA[c]);  accB[c] = ffma2(apC[3].y, p13, accB[c]);
                accA[c] = ffma2(apC[4].x, p12, accA[c]);  accB[c] = ffma2(apC[4].y, p14, accB[c]);
                c2q = n2q; c3q = n3q;
            }
        }

        affRow += WIN * HWSZ;
        sdy    += SPITCH;
    }

    // ---- write out --------------------------------------------------------
    float* outp = out + (size_t)b * CC * HWSZ + (y0 + yy) * WW + x0 + xs
                + (size_t)(c0 + ch * CPT) * HWSZ;
    #pragma unroll
    for (int c = 0; c < CPT; c++) {
        float4 v;
        unpackf2(accA[c], v.x, v.y);
        unpackf2(accB[c], v.z, v.w);
        *(float4*)(outp + (size_t)c * HWSZ) = v;
    }
}

extern "C" void kernel_launch(void* const* d_in, const int* in_sizes, int n_in,
                              void* d_out, int out_size)
{
    const float* aff = (const float*)d_in[0];   // [4,169,192,192]
    const float* in2 = (const float*)d_in[1];   // [4,64,192,192]
    float* out = (float*)d_out;                 // [4,64,192,192]

    dim3 grid(12, 24, 4);   // (cgroup*xtile, ytile, batch) — cgroup fastest for aff L2 reuse
    dim3 block(16, 16);
    mxassemble_kernel<<<grid, block>>>(aff, in2, out);
}

// round 17
// speedup vs baseline: 1.0368x; 1.0368x over previous
#include <cuda_runtime.h>

// MxAssemble: out[b,c,y,x] = sum_{dy,dx in [0,13)} aff[b, dy*13+dx, y, x] * in2zp[b, c, y+dy-6, x+dx-6]
// B=4, D=169, C=64, H=W=192, fp32.
// R15 structure (64x x 8y x 16ch tile, CPT=8, chunked dx A/B/C, apA
// double-buffered across dy) + CLEAN ping-pong of the smem quad loads across
// the channel loop via q[2] index arrays (constant indices after unroll ->
// no rotation MOVs, unlike R16). LDS for c+1 issues ~30 instrs before use.

#define BB   4
#define CC   64
#define HH   192
#define WW   192
#define WIN  13
#define DD   169
#define HWSZ (HH*WW)

#define TW    64     // x pixels per block
#define TH    8      // y rows per block
#define CBLK  16     // channels per block
#define CPT   8      // channels per thread
#define XR    4      // x pixels per thread
#define SROWS (TH+12)   // 20
#define SPITCH 80       // floats per smem row (320B, 16B aligned)
#define CSTRIDE (SROWS * SPITCH)

typedef unsigned long long u64t;

__device__ __forceinline__ u64t ffma2(u64t a, u64t b, u64t c) {
    u64t d;
    asm("fma.rn.f32x2 %0, %1, %2, %3;" : "=l"(d) : "l"(a), "l"(b), "l"(c));
    return d;
}
__device__ __forceinline__ u64t packf2(float lo, float hi) {
    u64t d;
    asm("mov.b64 %0, {%1, %2};" : "=l"(d) : "f"(lo), "f"(hi));
    return d;
}
__device__ __forceinline__ void unpackf2(u64t v, float& lo, float& hi) {
    asm("mov.b64 {%0, %1}, %2;" : "=f"(lo), "=f"(hi) : "l"(v));
}

union QU { ulonglong2 u; float4 f; };

__global__ __launch_bounds__(256, 2)
void mxassemble_kernel(const float* __restrict__ aff,
                       const float* __restrict__ in2,
                       float* __restrict__ out)
{
    __shared__ __align__(16) float s[CBLK][SROWS][SPITCH];   // 102,400 B

    const int tx = threadIdx.x;      // 0..15  -> x group
    const int ty = threadIdx.y;      // 0..15
    const int yy = ty & 7;           // row within tile
    const int ch = ty >> 3;          // channel half (0/1)

    const int bx = blockIdx.x;       // 12 = 4 cgroups * 3 xtiles, cgroup fastest
    const int cg = bx & 3;
    const int xt = bx >> 2;
    const int yt = blockIdx.y;       // 0..23
    const int b  = blockIdx.z;       // 0..3

    const int x0 = xt * TW;
    const int y0 = yt * TH;
    const int c0 = cg * CBLK;

    // ---- preload dy=0 chunk-A aff operands (independent of smem fill) -----
    const int xs = tx * XR;
    const float* affRow = aff + (size_t)b * DD * HWSZ + (y0 + yy) * WW + x0 + xs;

    ulonglong2 apA[4];
    #pragma unroll
    for (int j = 0; j < 4; j++)
        apA[j] = *(const ulonglong2*)(affRow + j * HWSZ);

    // ---- cooperative smem fill -------------------------------------------
    // 6400 quads = 16 planes x 20 rows x 20 aligned global quads (gxq = x0-8+4q).
    {
        const float* in2b = in2 + (size_t)b * CC * HWSZ;
        const int tid = ty * 16 + tx;
        int q  = tid % 20;
        int t2 = tid / 20;
        int rr = t2 % 20;
        int cc = t2 / 20;
        #pragma unroll 1
        for (int it = 0; it < 25; it++) {
            const int gy  = y0 - 6 + rr;
            const int gxq = x0 - 8 + 4 * q;

            float4 v = make_float4(0.f, 0.f, 0.f, 0.f);
            if ((unsigned)gy < (unsigned)HH) {
                const float* src = in2b + (size_t)(c0 + cc) * HWSZ + gy * WW + gxq;
                if (gxq >= 0 && gxq <= WW - 4) {
                    v = *(const float4*)src;
                } else {
                    if ((unsigned)(gxq + 0) < (unsigned)WW) v.x = src[0];
                    if ((unsigned)(gxq + 1) < (unsigned)WW) v.y = src[1];
                    if ((unsigned)(gxq + 2) < (unsigned)WW) v.z = src[2];
                    if ((unsigned)(gxq + 3) < (unsigned)WW) v.w = src[3];
                }
            }
            const int c0q = 4 * q - 2;               // smem col of v.x
            float* dst = &s[cc][rr][0];
            if (c0q >= 0) *(float2*)(dst + c0q) = make_float2(v.x, v.y);
            *(float2*)(dst + c0q + 2) = make_float2(v.z, v.w);

            // advance by 256 quads: 256 = 12*20 + 16
            q += 16; rr += 12;
            if (q >= 20)  { q -= 20; rr += 1; }
            if (rr >= 20) { rr -= 20; cc += 1; }
        }
    }
    __syncthreads();

    // ---- main accumulation ------------------------------------------------
    u64t accA[CPT], accB[CPT];       // accA: outputs (xs, xs+1), accB: (xs+2, xs+3)
    #pragma unroll
    for (int c = 0; c < CPT; c++) { accA[c] = 0ull; accB[c] = 0ull; }

    const float* sdy = &s[ch * CPT][0][0] + yy * SPITCH + xs;   // rolling smem base

    #pragma unroll 1
    for (int dy = 0; dy < WIN; dy++) {
        // issue chunk-B aff loads (consumed after chunk A)
        ulonglong2 apB[4];
        #pragma unroll
        for (int j = 0; j < 4; j++)
            apB[j] = *(const ulonglong2*)(affRow + (4 + j) * HWSZ);

        // ======== chunk A: j = 0..3 (quads Q0,Q1), c ping-ponged ===========
        {
            QU q0[2], q1[2];
            q0[0].u = *(const ulonglong2*)(sdy);
            q1[0].u = *(const ulonglong2*)(sdy + 4);
            #pragma unroll
            for (int c = 0; c < CPT; c++) {
                const int cur = c & 1, nxt = cur ^ 1;
                if (c < CPT - 1) {
                    const float* srn = sdy + (c + 1) * CSTRIDE;
                    q0[nxt].u = *(const ulonglong2*)(srn);
                    q1[nxt].u = *(const ulonglong2*)(srn + 4);
                }
                const u64t p0 = q0[cur].u.x, p2 = q0[cur].u.y, p4 = q1[cur].u.x;
                const u64t p1 = packf2(q0[cur].f.y, q0[cur].f.z);
                const u64t p3 = packf2(q0[cur].f.w, q1[cur].f.x);
                const u64t p5 = packf2(q1[cur].f.y, q1[cur].f.z);
                accA[c] = ffma2(apA[0].x, p0, accA[c]);  accB[c] = ffma2(apA[0].y, p2, accB[c]);
                accA[c] = ffma2(apA[1].x, p1, accA[c]);  accB[c] = ffma2(apA[1].y, p3, accB[c]);
                accA[c] = ffma2(apA[2].x, p2, accA[c]);  accB[c] = ffma2(apA[2].y, p4, accB[c]);
                accA[c] = ffma2(apA[3].x, p3, accA[c]);  accB[c] = ffma2(apA[3].y, p5, accB[c]);
            }
        }

        // issue chunk-C aff loads (consumed after chunk B)
        ulonglong2 apC[5];
        #pragma unroll
        for (int j = 0; j < 5; j++)
            apC[j] = *(const ulonglong2*)(affRow + (8 + j) * HWSZ);

        // prefetch next dy's chunk-A aff operands (consumed next iteration)
        if (dy < WIN - 1) {
            const float* nextRow = affRow + WIN * HWSZ;
            #pragma unroll
            for (int j = 0; j < 4; j++)
                apA[j] = *(const ulonglong2*)(nextRow + j * HWSZ);
        }

        // ======== chunk B: j = 4..7 (quads Q1,Q2), c ping-ponged ===========
        {
            QU q1[2], q2[2];
            q1[0].u = *(const ulonglong2*)(sdy + 4);
            q2[0].u = *(const ulonglong2*)(sdy + 8);
            #pragma unroll
            for (int c = 0; c < CPT; c++) {
                const int cur = c & 1, nxt = cur ^ 1;
                if (c < CPT - 1) {
                    const float* srn = sdy + (c + 1) * CSTRIDE;
                    q1[nxt].u = *(const ulonglong2*)(srn + 4);
                    q2[nxt].u = *(const ulonglong2*)(srn + 8);
                }
                const u64t p4 = q1[cur].u.x, p6 = q1[cur].u.y, p8 = q2[cur].u.x;
                const u64t p5 = packf2(q1[cur].f.y, q1[cur].f.z);
                const u64t p7 = packf2(q1[cur].f.w, q2[cur].f.x);
                const u64t p9 = packf2(q2[cur].f.y, q2[cur].f.z);
                accA[c] = ffma2(apB[0].x, p4, accA[c]);  accB[c] = ffma2(apB[0].y, p6, accB[c]);
                accA[c] = ffma2(apB[1].x, p5, accA[c]);  accB[c] = ffma2(apB[1].y, p7, accB[c]);
                accA[c] = ffma2(apB[2].x, p6, accA[c]);  accB[c] = ffma2(apB[2].y, p8, accB[c]);
                accA[c] = ffma2(apB[3].x, p7, accA[c]);  accB[c] = ffma2(apB[3].y, p9, accB[c]);
            }
        }

        // ======== chunk C: j = 8..12 (quads Q2,Q3), c ping-ponged ==========
        {
            QU q2[2], q3[2];
            q2[0].u = *(const ulonglong2*)(sdy + 8);
            q3[0].u = *(const ulonglong2*)(sdy + 12);
            #pragma unroll
            for (int c = 0; c < CPT; c++) {
                const int cur = c & 1, nxt = cur ^ 1;
                if (c < CPT - 1) {
                    const float* srn = sdy + (c + 1) * CSTRIDE;
                    q2[nxt].u = *(const ulonglong2*)(srn + 8);
                    q3[nxt].u = *(const ulonglong2*)(srn + 12);
                }
                const u64t p8 = q2[cur].u.x, p10 = q2[cur].u.y, p12 = q3[cur].u.x, p14 = q3[cur].u.y;
                const u64t p9  = packf2(q2[cur].f.y, q2[cur].f.z);
                const u64t p11 = packf2(q2[cur].f.w, q3[cur].f.x);
                const u64t p13 = packf2(q3[cur].f.y, q3[cur].f.z);
                accA[c] = ffma2(apC[0].x, p8,  accA[c]);  accB[c] = ffma2(apC[0].y, p10, accB[c]);
                accA[c] = ffma2(apC[1].x, p9,  accA[c]);  accB[c] = ffma2(apC[1].y, p11, accB[c]);
                accA[c] = ffma2(apC[2].x, p10, accA[c]);  accB[c] = ffma2(apC[2].y, p12, accB[c]);
                accA[c] = ffma2(apC[3].x, p11, accA[c]);  accB[c] = ffma2(apC[3].y, p13, accB[c]);
                accA[c] = ffma2(apC[4].x, p12, accA[c]);  accB[c] = ffma2(apC[4].y, p14, accB[c]);
            }
        }

        affRow += WIN * HWSZ;
        sdy    += SPITCH;
    }

    // ---- write out --------------------------------------------------------
    float* outp = out + (size_t)b * CC * HWSZ + (y0 + yy) * WW + x0 + xs
                + (size_t)(c0 + ch * CPT) * HWSZ;
    #pragma unroll
    for (int c = 0; c < CPT; c++) {
        float4 v;
        unpackf2(accA[c], v.x, v.y);
        unpackf2(accB[c], v.z, v.w);
        *(float4*)(outp + (size_t)c * HWSZ) = v;
    }
}

extern "C" void kernel_launch(void* const* d_in, const int* in_sizes, int n_in,
                              void* d_out, int out_size)
{
    const float* aff = (const float*)d_in[0];   // [4,169,192,192]
    const float* in2 = (const float*)d_in[1];   // [4,64,192,192]
    float* out = (float*)d_out;                 // [4,64,192,192]

    dim3 grid(12, 24, 4);   // (cgroup*xtile, ytile, batch) — cgroup fastest for aff L2 reuse
    dim3 block(16, 16);
    mxassemble_kernel<<<grid, block>>>(aff, in2, out);
}